// round 11
// baseline (speedup 1.0000x reference)
#include <cuda_runtime.h>

#define NN 50000
#define DD 128
#define EE 600000
#define GG 512
#define LLAYERS 3
#define EDIM 16
#define JKD 384
#define TILE_R 96
#define NODE_T 192
#define NTILES ((NN + TILE_R - 1) / TILE_R)
#define CHUNK 32

typedef unsigned long long u64;

// Scratch (device globals: no runtime allocation allowed)
__device__ float g_xcur[NN * DD];          // 25.6 MB
__device__ float g_agg[NN * DD];           // 25.6 MB (zeroed by node_kernel each layer)
__device__ float g_pool[GG * JKD];         // zeroed by head_kernel each call
__device__ int   g_cnt[NN];                // zeroed by k_scatter_init each call
__device__ int   g_cursor[NN];
__device__ int   g_csr_src[EE];
__device__ int   g_csr_dst[EE];
__device__ float g_csr_ea[(size_t)EE * EDIM];   // 38.4 MB, edge attrs in CSR order

// ---------------------------------------------------------------------------
// packed f32x2 helpers (sm_103a)
// ---------------------------------------------------------------------------
__device__ __forceinline__ u64 pack2(float x, float y) {
    u64 r; asm("mov.b64 %0, {%1, %2};" : "=l"(r) : "f"(x), "f"(y)); return r;
}
__device__ __forceinline__ float2 unpack2(u64 v) {
    float2 r; asm("mov.b64 {%0, %1}, %2;" : "=f"(r.x), "=f"(r.y) : "l"(v)); return r;
}
__device__ __forceinline__ void fma2(u64& d, u64 a, u64 b) {
    asm("fma.rn.f32x2 %0, %1, %2, %0;" : "+l"(d) : "l"(a), "l"(b));
}
__device__ __forceinline__ u64 add2(u64 a, u64 b) {
    u64 r; asm("add.rn.f32x2 %0, %1, %2;" : "=l"(r) : "l"(a), "l"(b)); return r;
}
__device__ __forceinline__ void red_v4(float* p, float4 v) {
    asm volatile("red.global.add.v4.f32 [%0], {%1,%2,%3,%4};"
                 :: "l"(p), "f"(v.x), "f"(v.y), "f"(v.z), "f"(v.w) : "memory");
}

// ---------------------------------------------------------------------------
// CSR build. hist(1) -> scan(2) -> scatter_init(3) -> agg is the profiled #4.
// g_cnt zeroed by the PREVIOUS call's scatter_init (module-load zero, call 1).
// ---------------------------------------------------------------------------
__global__ void k_hist(const int* __restrict__ ei) {
    int e = blockIdx.x * blockDim.x + threadIdx.x;
    if (e < EE) atomicAdd(&g_cnt[ei[EE + e]], 1);
}

__global__ __launch_bounds__(1024) void k_scan_single() {
    __shared__ int s[1024];
    const int t = threadIdx.x;
    const int per = (NN + 1023) / 1024;   // 49
    const int base = t * per;
    int lim = NN - base;
    if (lim < 0) lim = 0;
    if (lim > per) lim = per;
    int loc = 0;
    for (int i = 0; i < lim; i++) loc += g_cnt[base + i];
    s[t] = loc;
    __syncthreads();
#pragma unroll
    for (int o = 1; o < 1024; o <<= 1) {
        int u = (t >= o) ? s[t - o] : 0;
        __syncthreads();
        s[t] += u;
        __syncthreads();
    }
    int run = (t > 0) ? s[t - 1] : 0;   // exclusive prefix
    for (int i = 0; i < lim; i++) {
        const int c = g_cnt[base + i];
        g_cursor[base + i] = run;
        run += c;
    }
}

// scatter by dst (src, dst, attr copy) + x_cur = x + vn0 ; agg = 0 ; cnt = 0
__global__ void k_scatter_init(const int* __restrict__ ei, const float* __restrict__ ea,
                               const float* __restrict__ x, const float* __restrict__ vn0) {
    int i = blockIdx.x * blockDim.x + threadIdx.x;
    if (i < EE) {
        const int dst = ei[EE + i];
        const int pos = atomicAdd(&g_cursor[dst], 1);
        g_csr_src[pos] = ei[i];
        g_csr_dst[pos] = dst;
        const float4* q = reinterpret_cast<const float4*>(&ea[(size_t)i * EDIM]);
        float4* s = reinterpret_cast<float4*>(&g_csr_ea[(size_t)pos * EDIM]);
        s[0] = q[0]; s[1] = q[1]; s[2] = q[2]; s[3] = q[3];
    }
    if (i < NN) g_cnt[i] = 0;   // for next call's hist (scan already consumed it)
    if (i < NN * DD / 4) {
        float4 xv = reinterpret_cast<const float4*>(x)[i];
        float4 vv = reinterpret_cast<const float4*>(vn0)[i & 31];
        xv.x += vv.x; xv.y += vv.y; xv.z += vv.z; xv.w += vv.w;
        reinterpret_cast<float4*>(g_xcur)[i] = xv;
        reinterpret_cast<float4*>(g_agg)[i] = make_float4(0.f, 0.f, 0.f, 0.f);
    }
}

// ---------------------------------------------------------------------------
// Aggregation (R8 version, 101.5us measured twice): flat edge partition over
// dst-sorted CSR stream. Pairwise-k packed FMAs, attr pairs via LDS.64
// broadcast from a double-buffered per-warp smem stage, x[src] prefetched
// 2 deep (predicated). Flush on dst change: interior STG, boundaries RED.v4.
// ---------------------------------------------------------------------------
__global__ __launch_bounds__(256, 2) void agg_kernel(
    const float* __restrict__ ew, const float* __restrict__ ebias)
{
    __shared__ float s_attr[8][2][CHUNK * EDIM];   // 16 KB
    __shared__ int2  s_sd[8][2][CHUNK];            // 4 KB

    const int lane = threadIdx.x & 31;
    const int w = threadIdx.x >> 5;

    u64 wp[8][4];
#pragma unroll
    for (int j = 0; j < 8; j++)
#pragma unroll
        for (int c = 0; c < 4; c++)
            wp[j][c] = pack2(ew[(2 * j) * DD + lane * 4 + c],
                             ew[(2 * j + 1) * DD + lane * 4 + c]);
    const float4 bq = *reinterpret_cast<const float4*>(&ebias[lane * 4]);

    const int warp = (blockIdx.x * blockDim.x + threadIdx.x) >> 5;
    const int nw = (gridDim.x * blockDim.x) >> 5;
    const int epw = (EE + nw - 1) / nw;
    const int beg = warp * epw;
    if (beg >= EE) return;
    const int range = ((beg + epw < EE) ? beg + epw : EE) - beg;
    const int nchunks = (range + CHUNK - 1) / CHUNK;

    {
        const int cnt = (range < CHUNK) ? range : CHUNK;
        const float4* src4 = reinterpret_cast<const float4*>(&g_csr_ea[(size_t)beg * EDIM]);
        float4* dst4 = reinterpret_cast<float4*>(&s_attr[w][0][0]);
        for (int i = lane; i < cnt * 4; i += 32) dst4[i] = src4[i];
        if (lane < cnt) s_sd[w][0][lane] = make_int2(g_csr_src[beg + lane], g_csr_dst[beg + lane]);
    }
    __syncwarp();

    int2 sd0 = s_sd[w][0][0];
    int2 sd1 = (range > 1) ? s_sd[w][0][1] : sd0;
    float4 x0 = *reinterpret_cast<const float4*>(&g_xcur[(size_t)sd0.x * DD + lane * 4]);
    float4 x1 = (range > 1)
        ? *reinterpret_cast<const float4*>(&g_xcur[(size_t)sd1.x * DD + lane * 4]) : x0;

    float4 acc = make_float4(0.f, 0.f, 0.f, 0.f);
    int cur = sd0.y;
    bool firstflush = true;
    int gpos = 0;
    int buf = 0;

    for (int c = 0; c < nchunks; c++) {
        const int cbeg = c * CHUNK;
        const int cnt = ((range - cbeg) < CHUNK) ? (range - cbeg) : CHUNK;

        __syncwarp();
        if (c + 1 < nchunks) {
            const int nbeg = beg + cbeg + CHUNK;
            const int ncnt = ((range - cbeg - CHUNK) < CHUNK) ? (range - cbeg - CHUNK) : CHUNK;
            const float4* src4 = reinterpret_cast<const float4*>(&g_csr_ea[(size_t)nbeg * EDIM]);
            float4* dst4 = reinterpret_cast<float4*>(&s_attr[w][buf ^ 1][0]);
            for (int i = lane; i < ncnt * 4; i += 32) dst4[i] = src4[i];
            if (lane < ncnt)
                s_sd[w][buf ^ 1][lane] = make_int2(g_csr_src[nbeg + lane], g_csr_dst[nbeg + lane]);
        }
        __syncwarp();

        for (int i = 0; i < cnt; i++) {
            int2 sd2 = sd1;
            float4 x2 = make_float4(0.f, 0.f, 0.f, 0.f);
            if (gpos + 2 < range) {
                const int ii = i + 2;
                sd2 = (ii < cnt) ? s_sd[w][buf][ii] : s_sd[w][buf ^ 1][ii - cnt];
                x2 = *reinterpret_cast<const float4*>(&g_xcur[(size_t)sd2.x * DD + lane * 4]);
            }

            const u64* ap = reinterpret_cast<const u64*>(&s_attr[w][buf][i * EDIM]);
            u64 ac0 = pack2(bq.x, 0.f), ac1 = pack2(bq.y, 0.f);
            u64 ac2 = pack2(bq.z, 0.f), ac3 = pack2(bq.w, 0.f);
#pragma unroll
            for (int j = 0; j < 8; j++) {
                const u64 aj = ap[j];
                fma2(ac0, aj, wp[j][0]);
                fma2(ac1, aj, wp[j][1]);
                fma2(ac2, aj, wp[j][2]);
                fma2(ac3, aj, wp[j][3]);
            }
            const float2 q0 = unpack2(ac0), q1 = unpack2(ac1);
            const float2 q2 = unpack2(ac2), q3 = unpack2(ac3);
            const float m0 = fmaxf(q0.x + q0.y + x0.x, 0.f);
            const float m1 = fmaxf(q1.x + q1.y + x0.y, 0.f);
            const float m2 = fmaxf(q2.x + q2.y + x0.z, 0.f);
            const float m3 = fmaxf(q3.x + q3.y + x0.w, 0.f);

            if (sd0.y != cur) {   // warp-uniform
                float* p = &g_agg[(size_t)cur * DD + lane * 4];
                if (firstflush) red_v4(p, acc);
                else *reinterpret_cast<float4*>(p) = acc;
                firstflush = false;
                acc = make_float4(0.f, 0.f, 0.f, 0.f);
                cur = sd0.y;
            }
            acc.x += m0; acc.y += m1; acc.z += m2; acc.w += m3;

            x0 = x1; x1 = x2; sd0 = sd1; sd1 = sd2; gpos++;
        }
        buf ^= 1;
    }
    red_v4(&g_agg[(size_t)cur * DD + lane * 4], acc);
}

// ---------------------------------------------------------------------------
// Node MLP (fused, 8x8 per-thread tile — empirically the fastest config):
// h=(1+eps)*x+agg; y=relu(h@W1+b1); x2=y@W2+b2.
// 192 threads, TILE_R=96, both weight matrices resident in smem (224 KB).
// Fused epilogue: pool[batch[row]] += x2 (run-length RED.v4);
//                 x_cur = x2 + vn[l+1]; agg = 0 for next layer (except last).
// ---------------------------------------------------------------------------
__device__ __forceinline__ void tile_gemm8(
    const float* sA, const float* sW, int cg, int rg, u64 acc[8][4])
{
#pragma unroll 1
    for (int k = 0; k < DD; k += 4) {
        u64 w[4][4];
#pragma unroll
        for (int kk = 0; kk < 4; kk++) {
            const float4 wa = *reinterpret_cast<const float4*>(&sW[(k + kk) * DD + cg * 8]);
            const float4 wb = *reinterpret_cast<const float4*>(&sW[(k + kk) * DD + cg * 8 + 4]);
            w[kk][0] = pack2(wa.x, wa.y);
            w[kk][1] = pack2(wa.z, wa.w);
            w[kk][2] = pack2(wb.x, wb.y);
            w[kk][3] = pack2(wb.z, wb.w);
        }
        float4 a[8];
#pragma unroll
        for (int r = 0; r < 8; r++)
            a[r] = *reinterpret_cast<const float4*>(&sA[(rg * 8 + r) * DD + k]);
#pragma unroll
        for (int r = 0; r < 8; r++) {
            const u64 ax = pack2(a[r].x, a[r].x);
            fma2(acc[r][0], ax, w[0][0]); fma2(acc[r][1], ax, w[0][1]);
            fma2(acc[r][2], ax, w[0][2]); fma2(acc[r][3], ax, w[0][3]);
            const u64 ay = pack2(a[r].y, a[r].y);
            fma2(acc[r][0], ay, w[1][0]); fma2(acc[r][1], ay, w[1][1]);
            fma2(acc[r][2], ay, w[1][2]); fma2(acc[r][3], ay, w[1][3]);
            const u64 az = pack2(a[r].z, a[r].z);
            fma2(acc[r][0], az, w[2][0]); fma2(acc[r][1], az, w[2][1]);
            fma2(acc[r][2], az, w[2][2]); fma2(acc[r][3], az, w[2][3]);
            const u64 aw = pack2(a[r].w, a[r].w);
            fma2(acc[r][0], aw, w[3][0]); fma2(acc[r][1], aw, w[3][1]);
            fma2(acc[r][2], aw, w[3][2]); fma2(acc[r][3], aw, w[3][3]);
        }
    }
}

__global__ __launch_bounds__(NODE_T) void node_kernel(
    const float* __restrict__ w1, const float* __restrict__ b1,
    const float* __restrict__ w2, const float* __restrict__ b2,
    const float* __restrict__ epsp, const float* __restrict__ vn_next,
    const int* __restrict__ batch, int layer)
{
    extern __shared__ float sm[];
    float* sW1 = sm;                          // 64 KB
    float* sW2 = sm + DD * DD;                // 64 KB
    float* sH  = sm + 2 * DD * DD;            // 48 KB
    float* sY  = sH + TILE_R * DD;            // 48 KB
    int*   sB  = reinterpret_cast<int*>(sY + TILE_R * DD);  // 384 B
    const int t = threadIdx.x;

    for (int i = t; i < DD * DD / 4; i += NODE_T) {
        reinterpret_cast<float4*>(sW1)[i] = reinterpret_cast<const float4*>(w1)[i];
        reinterpret_cast<float4*>(sW2)[i] = reinterpret_cast<const float4*>(w2)[i];
    }
    const float epsv = 1.0f + *epsp;
    const int cg = t & 15;   // col group: 8 cols
    const int rg = t >> 4;   // row group: 8 rows (12 groups x 8 = 96)

    const float4 b1a = *reinterpret_cast<const float4*>(&b1[cg * 8]);
    const float4 b1b = *reinterpret_cast<const float4*>(&b1[cg * 8 + 4]);
    const float4 b2a = *reinterpret_cast<const float4*>(&b2[cg * 8]);
    const float4 b2b = *reinterpret_cast<const float4*>(&b2[cg * 8 + 4]);

    float4 vna = make_float4(0.f, 0.f, 0.f, 0.f), vnb = vna;
    if (vn_next) {
        vna = *reinterpret_cast<const float4*>(&vn_next[cg * 8]);
        vnb = *reinterpret_cast<const float4*>(&vn_next[cg * 8 + 4]);
    }
    const int zero_agg = (vn_next != nullptr);

    for (int tile = blockIdx.x; tile < NTILES; tile += gridDim.x) {
        const int row0 = tile * TILE_R;
        __syncthreads();   // protect sH/sY/sB reuse; also fences weight load (iter 0)

        // h tile = (1+eps)*x + agg ; stage batch ids; zero agg for next layer
        for (int i = t; i < TILE_R; i += NODE_T)
            sB[i] = (row0 + i < NN) ? batch[row0 + i] : -1;
        for (int i = t; i < TILE_R * DD / 4; i += NODE_T) {
            const int row = row0 + (i >> 5);
            float4 hv = make_float4(0.f, 0.f, 0.f, 0.f);
            if (row < NN) {
                const int gi = row0 * (DD / 4) + i;
                const float4 xv = reinterpret_cast<const float4*>(g_xcur)[gi];
                const float4 av = reinterpret_cast<const float4*>(g_agg)[gi];
                hv.x = fmaf(epsv, xv.x, av.x);
                hv.y = fmaf(epsv, xv.y, av.y);
                hv.z = fmaf(epsv, xv.z, av.z);
                hv.w = fmaf(epsv, xv.w, av.w);
                if (zero_agg)
                    reinterpret_cast<float4*>(g_agg)[gi] = make_float4(0.f, 0.f, 0.f, 0.f);
            }
            reinterpret_cast<float4*>(sH)[i] = hv;
        }
        __syncthreads();

        u64 acc[8][4];
#pragma unroll
        for (int r = 0; r < 8; r++) {
            acc[r][0] = pack2(b1a.x, b1a.y); acc[r][1] = pack2(b1a.z, b1a.w);
            acc[r][2] = pack2(b1b.x, b1b.y); acc[r][3] = pack2(b1b.z, b1b.w);
        }
        tile_gemm8(sH, sW1, cg, rg, acc);
#pragma unroll
        for (int r = 0; r < 8; r++) {
            float* dst = &sY[(rg * 8 + r) * DD + cg * 8];
            const float2 p0 = unpack2(acc[r][0]), p1 = unpack2(acc[r][1]);
            const float2 p2 = unpack2(acc[r][2]), p3 = unpack2(acc[r][3]);
            *reinterpret_cast<float4*>(dst) =
                make_float4(fmaxf(p0.x, 0.f), fmaxf(p0.y, 0.f),
                            fmaxf(p1.x, 0.f), fmaxf(p1.y, 0.f));
            *reinterpret_cast<float4*>(dst + 4) =
                make_float4(fmaxf(p2.x, 0.f), fmaxf(p2.y, 0.f),
                            fmaxf(p3.x, 0.f), fmaxf(p3.y, 0.f));
        }
        __syncthreads();

#pragma unroll
        for (int r = 0; r < 8; r++) {
            acc[r][0] = pack2(b2a.x, b2a.y); acc[r][1] = pack2(b2a.z, b2a.w);
            acc[r][2] = pack2(b2b.x, b2b.y); acc[r][3] = pack2(b2b.z, b2b.w);
        }
        tile_gemm8(sY, sW2, cg, rg, acc);

        // Epilogue: pool RED (run-length reduced over sorted batch) + x_cur
        u64 ps0 = 0, ps1 = 0, ps2 = 0, ps3 = 0;
        int curb = -1;
#pragma unroll
        for (int r = 0; r < 8; r++) {
            const int lrow = rg * 8 + r;
            const int row = row0 + lrow;
            if (row >= NN) break;
            const int b = sB[lrow];
            if (b != curb) {
                if (curb >= 0) {
                    float* p = &g_pool[curb * JKD + layer * DD + cg * 8];
                    const float2 q0 = unpack2(ps0), q1 = unpack2(ps1);
                    const float2 q2 = unpack2(ps2), q3 = unpack2(ps3);
                    red_v4(p, make_float4(q0.x, q0.y, q1.x, q1.y));
                    red_v4(p + 4, make_float4(q2.x, q2.y, q3.x, q3.y));
                }
                curb = b; ps0 = ps1 = ps2 = ps3 = 0;
            }
            ps0 = add2(ps0, acc[r][0]); ps1 = add2(ps1, acc[r][1]);
            ps2 = add2(ps2, acc[r][2]); ps3 = add2(ps3, acc[r][3]);

            if (vn_next) {
                const float2 p0 = unpack2(acc[r][0]), p1 = unpack2(acc[r][1]);
                const float2 p2 = unpack2(acc[r][2]), p3 = unpack2(acc[r][3]);
                float* dst = &g_xcur[(size_t)row * DD + cg * 8];
                *reinterpret_cast<float4*>(dst) =
                    make_float4(p0.x + vna.x, p0.y + vna.y, p1.x + vna.z, p1.y + vna.w);
                *reinterpret_cast<float4*>(dst + 4) =
                    make_float4(p2.x + vnb.x, p2.y + vnb.y, p3.x + vnb.z, p3.y + vnb.w);
            }
        }
        if (curb >= 0) {
            float* p = &g_pool[curb * JKD + layer * DD + cg * 8];
            const float2 q0 = unpack2(ps0), q1 = unpack2(ps1);
            const float2 q2 = unpack2(ps2), q3 = unpack2(ps3);
            red_v4(p, make_float4(q0.x, q0.y, q1.x, q1.y));
            red_v4(p + 4, make_float4(q2.x, q2.y, q3.x, q3.y));
        }
    }
}

// ---------------------------------------------------------------------------
// Head: Linear(384->256) -> LN -> ReLU -> Linear(256->128) -> LN -> ReLU -> Linear(128->1)
// Also re-zeroes its g_pool row for the next call (graph-replay determinism).
// ---------------------------------------------------------------------------
__device__ __forceinline__ float2 block_sum2(float a, float b) {
    __shared__ float2 sred[8];
    const int lane = threadIdx.x & 31, w = threadIdx.x >> 5;
#pragma unroll
    for (int o = 16; o; o >>= 1) {
        a += __shfl_down_sync(0xffffffffu, a, o);
        b += __shfl_down_sync(0xffffffffu, b, o);
    }
    if (lane == 0) sred[w] = make_float2(a, b);
    __syncthreads();
    if (w == 0) {
        float2 s = (lane < 8) ? sred[lane] : make_float2(0.f, 0.f);
#pragma unroll
        for (int o = 4; o; o >>= 1) {
            s.x += __shfl_down_sync(0xffffffffu, s.x, o);
            s.y += __shfl_down_sync(0xffffffffu, s.y, o);
        }
        if (lane == 0) sred[0] = s;
    }
    __syncthreads();
    const float2 r = sred[0];
    __syncthreads();
    return r;
}

__global__ __launch_bounds__(256) void head_kernel(
    const float* __restrict__ w1, const float* __restrict__ b1,
    const float* __restrict__ ga1, const float* __restrict__ be1,
    const float* __restrict__ w2, const float* __restrict__ b2,
    const float* __restrict__ ga2, const float* __restrict__ be2,
    const float* __restrict__ ow, const float* __restrict__ ob,
    float* __restrict__ out)
{
    __shared__ float sg[JKD];
    __shared__ float s1[256];
    const int g = blockIdx.x, t = threadIdx.x;

    for (int i = t; i < JKD; i += 256) {
        sg[i] = g_pool[g * JKD + i];
        g_pool[g * JKD + i] = 0.f;   // re-zero for next call
    }
    __syncthreads();

    float acc = b1[t];
#pragma unroll 4
    for (int k = 0; k < JKD; k++) acc = fmaf(sg[k], w1[k * 256 + t], acc);
    float2 s = block_sum2(acc, acc * acc);
    float mu = s.x * (1.f / 256.f);
    float var = s.y * (1.f / 256.f) - mu * mu;
    s1[t] = fmaxf((acc - mu) * rsqrtf(var + 1e-5f) * ga1[t] + be1[t], 0.f);
    __syncthreads();

    float acc2 = 0.f;
    if (t < 128) {
        acc2 = b2[t];
#pragma unroll 4
        for (int k = 0; k < 256; k++) acc2 = fmaf(s1[k], w2[k * 128 + t], acc2);
    }
    const float cva = (t < 128) ? acc2 : 0.f;
    float2 s2 = block_sum2(cva, cva * cva);
    float mu2 = s2.x * (1.f / 128.f);
    float var2 = s2.y * (1.f / 128.f) - mu2 * mu2;
    float v2 = 0.f;
    if (t < 128) v2 = fmaxf((acc2 - mu2) * rsqrtf(var2 + 1e-5f) * ga2[t] + be2[t], 0.f);

    const float p = (t < 128) ? v2 * ow[t] : 0.f;
    float2 s3 = block_sum2(p, 0.f);
    if (t == 0) out[g] = s3.x + ob[0];
}

// ---------------------------------------------------------------------------
extern "C" void kernel_launch(void* const* d_in, const int* in_sizes, int n_in,
                              void* d_out, int out_size) {
    (void)in_sizes; (void)n_in; (void)out_size;
    const float* x     = (const float*)d_in[0];
    const int*   ei    = (const int*)d_in[1];
    const float* ea    = (const float*)d_in[2];
    const int*   batch = (const int*)d_in[3];
    const float* vn    = (const float*)d_in[4];
    const float* ew    = (const float*)d_in[5];
    const float* ebias = (const float*)d_in[6];
    const float* eps   = (const float*)d_in[7];
    const float* mw1   = (const float*)d_in[8];
    const float* mb1   = (const float*)d_in[9];
    const float* mw2   = (const float*)d_in[10];
    const float* mb2   = (const float*)d_in[11];
    const float* lw1   = (const float*)d_in[12];
    const float* lb1   = (const float*)d_in[13];
    const float* ln1g  = (const float*)d_in[14];
    const float* ln1b  = (const float*)d_in[15];
    const float* lw2   = (const float*)d_in[16];
    const float* lb2   = (const float*)d_in[17];
    const float* ln2g  = (const float*)d_in[18];
    const float* ln2b  = (const float*)d_in[19];
    const float* ow    = (const float*)d_in[20];
    const float* ob    = (const float*)d_in[21];
    float* out = (float*)d_out;

    int nsm = 148;
    cudaDeviceGetAttribute(&nsm, cudaDevAttrMultiProcessorCount, 0);

    const int node_smem = (2 * DD * DD + 2 * TILE_R * DD) * (int)sizeof(float)
                        + TILE_R * (int)sizeof(int);                    // ~224.4 KB
    cudaFuncSetAttribute(node_kernel, cudaFuncAttributeMaxDynamicSharedMemorySize, node_smem);

    // CSR build + init (agg_kernel is launch #4, the one ncu captures).
    k_hist<<<(EE + 255) / 256, 256>>>(ei);
    k_scan_single<<<1, 1024>>>();
    k_scatter_init<<<(NN * DD / 4 + 255) / 256, 256>>>(ei, ea, x, vn);

    for (int i = 0; i < LLAYERS; i++) {
        agg_kernel<<<nsm * 2, 256>>>(ew + i * EDIM * DD, ebias + i * DD);
        node_kernel<<<nsm, NODE_T, node_smem>>>(
            mw1 + i * DD * DD, mb1 + i * DD,
            mw2 + i * DD * DD, mb2 + i * DD,
            eps + i,
            (i < LLAYERS - 1) ? (vn + (i + 1) * DD) : nullptr,
            batch, i);
    }

    head_kernel<<<GG, 256>>>(lw1, lb1, ln1g, ln1b, lw2, lb2, ln2g, ln2b, ow, ob, out);
}

// round 13
// speedup vs baseline: 1.1774x; 1.1774x over previous
#include <cuda_runtime.h>
#include <cuda_bf16.h>
#include <mma.h>

using namespace nvcuda;

#define NN 50000
#define DD 128
#define EE 600000
#define GG 512
#define LLAYERS 3
#define EDIM 16
#define JKD 384
#define CHUNK 32
#define TROWS 64
#define NT64 ((NN + TROWS - 1) / TROWS)
#define WS 136   // bf16 smem stride (elems): 272B rows, frag ptrs 32B-aligned
#define CS 136   // f32 staging stride

typedef unsigned long long u64;
typedef unsigned int u32;

// Scratch (device globals: no runtime allocation allowed)
__device__ float g_xcur[NN * DD];          // 25.6 MB
__device__ float g_agg[NN * DD];           // (zeroed by node each layer / scatter_init)
__device__ float g_pool[GG * JKD];         // zeroed by head_kernel each call
__device__ int   g_cnt[NN];                // zeroed by k_scatter_init each call
__device__ int   g_cursor[NN];
__device__ int   g_csr_src[EE];
__device__ int   g_csr_dst[EE];
__device__ float g_csr_ea[(size_t)EE * EDIM];

// ---------------------------------------------------------------------------
// packed f32x2 helpers (sm_103a)
// ---------------------------------------------------------------------------
__device__ __forceinline__ u64 pack2(float x, float y) {
    u64 r; asm("mov.b64 %0, {%1, %2};" : "=l"(r) : "f"(x), "f"(y)); return r;
}
__device__ __forceinline__ float2 unpack2(u64 v) {
    float2 r; asm("mov.b64 {%0, %1}, %2;" : "=f"(r.x), "=f"(r.y) : "l"(v)); return r;
}
__device__ __forceinline__ void fma2(u64& d, u64 a, u64 b) {
    asm("fma.rn.f32x2 %0, %1, %2, %0;" : "+l"(d) : "l"(a), "l"(b));
}
__device__ __forceinline__ void red_v4(float* p, float4 v) {
    asm volatile("red.global.add.v4.f32 [%0], {%1,%2,%3,%4};"
                 :: "l"(p), "f"(v.x), "f"(v.y), "f"(v.z), "f"(v.w) : "memory");
}
__device__ __forceinline__ void red_v2(float* p, float x, float y) {
    asm volatile("red.global.add.v2.f32 [%0], {%1,%2};"
                 :: "l"(p), "f"(x), "f"(y) : "memory");
}

// ---------------------------------------------------------------------------
// CSR build. hist(1) -> scan(2) -> scatter_init(3) -> agg is profiled #4.
// g_cnt zeroed by the PREVIOUS call's scatter_init (module-load zero, call 1).
// ---------------------------------------------------------------------------
__global__ void k_hist(const int* __restrict__ ei) {
    int e = blockIdx.x * blockDim.x + threadIdx.x;
    if (e < EE) atomicAdd(&g_cnt[ei[EE + e]], 1);
}

__global__ __launch_bounds__(1024) void k_scan_single() {
    __shared__ int s[1024];
    const int t = threadIdx.x;
    const int per = (NN + 1023) / 1024;
    const int base = t * per;
    int lim = NN - base;
    if (lim < 0) lim = 0;
    if (lim > per) lim = per;
    int loc = 0;
    for (int i = 0; i < lim; i++) loc += g_cnt[base + i];
    s[t] = loc;
    __syncthreads();
#pragma unroll
    for (int o = 1; o < 1024; o <<= 1) {
        int u = (t >= o) ? s[t - o] : 0;
        __syncthreads();
        s[t] += u;
        __syncthreads();
    }
    int run = (t > 0) ? s[t - 1] : 0;
    for (int i = 0; i < lim; i++) {
        const int c = g_cnt[base + i];
        g_cursor[base + i] = run;
        run += c;
    }
}

__global__ void k_scatter_init(const int* __restrict__ ei, const float* __restrict__ ea,
                               const float* __restrict__ x, const float* __restrict__ vn0) {
    int i = blockIdx.x * blockDim.x + threadIdx.x;
    if (i < EE) {
        const int dst = ei[EE + i];
        const int pos = atomicAdd(&g_cursor[dst], 1);
        g_csr_src[pos] = ei[i];
        g_csr_dst[pos] = dst;
        const float4* q = reinterpret_cast<const float4*>(&ea[(size_t)i * EDIM]);
        float4* s = reinterpret_cast<float4*>(&g_csr_ea[(size_t)pos * EDIM]);
        s[0] = q[0]; s[1] = q[1]; s[2] = q[2]; s[3] = q[3];
    }
    if (i < NN) g_cnt[i] = 0;
    if (i < NN * DD / 4) {
        float4 xv = reinterpret_cast<const float4*>(x)[i];
        float4 vv = reinterpret_cast<const float4*>(vn0)[i & 31];
        xv.x += vv.x; xv.y += vv.y; xv.z += vv.z; xv.w += vv.w;
        reinterpret_cast<float4*>(g_xcur)[i] = xv;
        reinterpret_cast<float4*>(g_agg)[i] = make_float4(0.f, 0.f, 0.f, 0.f);
    }
}

// ---------------------------------------------------------------------------
// Aggregation (R8/R11 version, measured 101.5us three times — unchanged)
// ---------------------------------------------------------------------------
__global__ __launch_bounds__(256, 2) void agg_kernel(
    const float* __restrict__ ew, const float* __restrict__ ebias)
{
    __shared__ float s_attr[8][2][CHUNK * EDIM];
    __shared__ int2  s_sd[8][2][CHUNK];

    const int lane = threadIdx.x & 31;
    const int w = threadIdx.x >> 5;

    u64 wp[8][4];
#pragma unroll
    for (int j = 0; j < 8; j++)
#pragma unroll
        for (int c = 0; c < 4; c++)
            wp[j][c] = pack2(ew[(2 * j) * DD + lane * 4 + c],
                             ew[(2 * j + 1) * DD + lane * 4 + c]);
    const float4 bq = *reinterpret_cast<const float4*>(&ebias[lane * 4]);

    const int warp = (blockIdx.x * blockDim.x + threadIdx.x) >> 5;
    const int nw = (gridDim.x * blockDim.x) >> 5;
    const int epw = (EE + nw - 1) / nw;
    const int beg = warp * epw;
    if (beg >= EE) return;
    const int range = ((beg + epw < EE) ? beg + epw : EE) - beg;
    const int nchunks = (range + CHUNK - 1) / CHUNK;

    {
        const int cnt = (range < CHUNK) ? range : CHUNK;
        const float4* src4 = reinterpret_cast<const float4*>(&g_csr_ea[(size_t)beg * EDIM]);
        float4* dst4 = reinterpret_cast<float4*>(&s_attr[w][0][0]);
        for (int i = lane; i < cnt * 4; i += 32) dst4[i] = src4[i];
        if (lane < cnt) s_sd[w][0][lane] = make_int2(g_csr_src[beg + lane], g_csr_dst[beg + lane]);
    }
    __syncwarp();

    int2 sd0 = s_sd[w][0][0];
    int2 sd1 = (range > 1) ? s_sd[w][0][1] : sd0;
    float4 x0 = *reinterpret_cast<const float4*>(&g_xcur[(size_t)sd0.x * DD + lane * 4]);
    float4 x1 = (range > 1)
        ? *reinterpret_cast<const float4*>(&g_xcur[(size_t)sd1.x * DD + lane * 4]) : x0;

    float4 acc = make_float4(0.f, 0.f, 0.f, 0.f);
    int cur = sd0.y;
    bool firstflush = true;
    int gpos = 0;
    int buf = 0;

    for (int c = 0; c < nchunks; c++) {
        const int cbeg = c * CHUNK;
        const int cnt = ((range - cbeg) < CHUNK) ? (range - cbeg) : CHUNK;

        __syncwarp();
        if (c + 1 < nchunks) {
            const int nbeg = beg + cbeg + CHUNK;
            const int ncnt = ((range - cbeg - CHUNK) < CHUNK) ? (range - cbeg - CHUNK) : CHUNK;
            const float4* src4 = reinterpret_cast<const float4*>(&g_csr_ea[(size_t)nbeg * EDIM]);
            float4* dst4 = reinterpret_cast<float4*>(&s_attr[w][buf ^ 1][0]);
            for (int i = lane; i < ncnt * 4; i += 32) dst4[i] = src4[i];
            if (lane < ncnt)
                s_sd[w][buf ^ 1][lane] = make_int2(g_csr_src[nbeg + lane], g_csr_dst[nbeg + lane]);
        }
        __syncwarp();

        for (int i = 0; i < cnt; i++) {
            int2 sd2 = sd1;
            float4 x2 = make_float4(0.f, 0.f, 0.f, 0.f);
            if (gpos + 2 < range) {
                const int ii = i + 2;
                sd2 = (ii < cnt) ? s_sd[w][buf][ii] : s_sd[w][buf ^ 1][ii - cnt];
                x2 = *reinterpret_cast<const float4*>(&g_xcur[(size_t)sd2.x * DD + lane * 4]);
            }

            const u64* ap = reinterpret_cast<const u64*>(&s_attr[w][buf][i * EDIM]);
            u64 ac0 = pack2(bq.x, 0.f), ac1 = pack2(bq.y, 0.f);
            u64 ac2 = pack2(bq.z, 0.f), ac3 = pack2(bq.w, 0.f);
#pragma unroll
            for (int j = 0; j < 8; j++) {
                const u64 aj = ap[j];
                fma2(ac0, aj, wp[j][0]);
                fma2(ac1, aj, wp[j][1]);
                fma2(ac2, aj, wp[j][2]);
                fma2(ac3, aj, wp[j][3]);
            }
            const float2 q0 = unpack2(ac0), q1 = unpack2(ac1);
            const float2 q2 = unpack2(ac2), q3 = unpack2(ac3);
            const float m0 = fmaxf(q0.x + q0.y + x0.x, 0.f);
            const float m1 = fmaxf(q1.x + q1.y + x0.y, 0.f);
            const float m2 = fmaxf(q2.x + q2.y + x0.z, 0.f);
            const float m3 = fmaxf(q3.x + q3.y + x0.w, 0.f);

            if (sd0.y != cur) {
                float* p = &g_agg[(size_t)cur * DD + lane * 4];
                if (firstflush) red_v4(p, acc);
                else *reinterpret_cast<float4*>(p) = acc;
                firstflush = false;
                acc = make_float4(0.f, 0.f, 0.f, 0.f);
                cur = sd0.y;
            }
            acc.x += m0; acc.y += m1; acc.z += m2; acc.w += m3;

            x0 = x1; x1 = x2; sd0 = sd1; sd1 = sd2; gpos++;
        }
        buf ^= 1;
    }
    red_v4(&g_agg[(size_t)cur * DD + lane * 4], acc);
}

// ---------------------------------------------------------------------------
// Node MLP on WMMA bf16 (sm_103-legal tensor path).
// 2-term bf16 split per operand; D = Ah*Bh + Ah*Bl + Al*Bh (fp32 accum).
// 256 threads (8 warps as 4 row-stripes x 2 col-halves), 64-row tiles,
// persistent 1 CTA/SM. W1/W2 hi+lo resident in smem for the whole kernel.
//   stage h=(1+eps)x+agg -> split -> A bufs; GEMM1 -> C; bias+relu+split -> A;
//   GEMM2 -> C; epilogue: pool RED (run-length) + x_cur + vn; agg=0 fused.
// ---------------------------------------------------------------------------
__global__ __launch_bounds__(256, 1) void node_wmma(
    const float* __restrict__ w1, const float* __restrict__ b1,
    const float* __restrict__ w2, const float* __restrict__ b2,
    const float* __restrict__ epsp, const float* __restrict__ vn_next,
    const int* __restrict__ batch, int layer)
{
    extern __shared__ __align__(32) char dyn[];
    __nv_bfloat16* sW1h = reinterpret_cast<__nv_bfloat16*>(dyn);                 // 34816 B
    __nv_bfloat16* sW1l = sW1h + DD * WS;
    __nv_bfloat16* sW2h = sW1l + DD * WS;
    __nv_bfloat16* sW2l = sW2h + DD * WS;
    __nv_bfloat16* sAh  = sW2l + DD * WS;                                        // 17408 B
    __nv_bfloat16* sAl  = sAh + TROWS * WS;
    float* sC = reinterpret_cast<float*>(sAl + TROWS * WS);                      // 34816 B

    __shared__ float b1s[DD], b2s[DD];
    __shared__ int sB[TROWS];

    const int t = threadIdx.x;
    const int wid = t >> 5;

    // ---- load weights once (transposed layout not needed: W[k][n] row-major) ----
    for (int idx = t; idx < DD * DD; idx += 256) {
        const int k = idx >> 7, n = idx & 127;
        float v = w1[idx];
        __nv_bfloat16 h = __float2bfloat16(v);
        sW1h[k * WS + n] = h;
        sW1l[k * WS + n] = __float2bfloat16(v - __bfloat162float(h));
        v = w2[idx];
        h = __float2bfloat16(v);
        sW2h[k * WS + n] = h;
        sW2l[k * WS + n] = __float2bfloat16(v - __bfloat162float(h));
    }
    if (t < DD) { b1s[t] = b1[t]; b2s[t] = b2[t]; }
    const float epsv = 1.0f + *epsp;

    // warp tile assignment: rows [rs*16, rs*16+16), cols [ch*64, ch*64+64)
    const int rs = wid >> 1;
    const int ch = wid & 1;
    const int r0 = rs * 16;
    const int c0 = ch * 64;

    // epilogue: thread t -> cols {2*col2, 2*col2+1}, rows [seg*16, seg*16+16)
    const int col2 = t & 63;
    const int seg = t >> 6;
    float2 vn2 = make_float2(0.f, 0.f);
    if (vn_next) vn2 = *reinterpret_cast<const float2*>(&vn_next[2 * col2]);
    const int zero_agg = (vn_next != nullptr);

    for (int tile = blockIdx.x; tile < NT64; tile += gridDim.x) {
        const int row0 = tile * TROWS;
        __syncthreads();   // buffer reuse guard across tiles

        // ---- stage h = (1+eps)x + agg; split -> sAh/sAl; zero agg; batch ----
        for (int i = t; i < TROWS; i += 256)
            sB[i] = (row0 + i < NN) ? batch[row0 + i] : -1;
        for (int i = t; i < TROWS * (DD / 4); i += 256) {
            const int row = i >> 5, c4 = (i & 31) * 4;
            const int grow = row0 + row;
            float4 hv = make_float4(0.f, 0.f, 0.f, 0.f);
            if (grow < NN) {
                const int gi = row0 * (DD / 4) + i;
                const float4 xv = reinterpret_cast<const float4*>(g_xcur)[gi];
                const float4 av = reinterpret_cast<const float4*>(g_agg)[gi];
                hv.x = fmaf(epsv, xv.x, av.x);
                hv.y = fmaf(epsv, xv.y, av.y);
                hv.z = fmaf(epsv, xv.z, av.z);
                hv.w = fmaf(epsv, xv.w, av.w);
                if (zero_agg)
                    reinterpret_cast<float4*>(g_agg)[gi] = make_float4(0.f, 0.f, 0.f, 0.f);
            }
            __nv_bfloat16* ph = &sAh[row * WS + c4];
            __nv_bfloat16* pl = &sAl[row * WS + c4];
            const float f[4] = {hv.x, hv.y, hv.z, hv.w};
#pragma unroll
            for (int j = 0; j < 4; j++) {
                const __nv_bfloat16 hi = __float2bfloat16(f[j]);
                ph[j] = hi;
                pl[j] = __float2bfloat16(f[j] - __bfloat162float(hi));
            }
        }
        __syncthreads();

        // ---- GEMM1: C = Ah*W1h + Ah*W1l + Al*W1h ----
        {
            wmma::fragment<wmma::accumulator, 16, 16, 16, float> acc[4];
#pragma unroll
            for (int j = 0; j < 4; j++) wmma::fill_fragment(acc[j], 0.f);
#pragma unroll
            for (int p = 0; p < 3; p++) {
                const __nv_bfloat16* As = (p == 2) ? sAl : sAh;
                const __nv_bfloat16* Bs = (p == 1) ? sW1l : sW1h;
                for (int k = 0; k < 8; k++) {
                    wmma::fragment<wmma::matrix_a, 16, 16, 16, __nv_bfloat16, wmma::row_major> af;
                    wmma::load_matrix_sync(af, &As[r0 * WS + k * 16], WS);
#pragma unroll
                    for (int j = 0; j < 4; j++) {
                        wmma::fragment<wmma::matrix_b, 16, 16, 16, __nv_bfloat16, wmma::row_major> bf;
                        wmma::load_matrix_sync(bf, &Bs[k * 16 * WS + c0 + j * 16], WS);
                        wmma::mma_sync(acc[j], af, bf, acc[j]);
                    }
                }
            }
#pragma unroll
            for (int j = 0; j < 4; j++)
                wmma::store_matrix_sync(&sC[r0 * CS + c0 + j * 16], acc[j], CS,
                                        wmma::mem_row_major);
        }
        __syncthreads();

        // ---- y = relu(C + b1); split -> sAh/sAl ----
        for (int i = t; i < TROWS * (DD / 2); i += 256) {
            const int row = i >> 6, c2 = (i & 63) * 2;
            const float y0 = fmaxf(sC[row * CS + c2] + b1s[c2], 0.f);
            const float y1 = fmaxf(sC[row * CS + c2 + 1] + b1s[c2 + 1], 0.f);
            const __nv_bfloat16 h0 = __float2bfloat16(y0);
            const __nv_bfloat16 h1 = __float2bfloat16(y1);
            sAh[row * WS + c2] = h0;
            sAh[row * WS + c2 + 1] = h1;
            sAl[row * WS + c2] = __float2bfloat16(y0 - __bfloat162float(h0));
            sAl[row * WS + c2 + 1] = __float2bfloat16(y1 - __bfloat162float(h1));
        }
        __syncthreads();

        // ---- GEMM2: C = Ah*W2h + Ah*W2l + Al*W2h ----
        {
            wmma::fragment<wmma::accumulator, 16, 16, 16, float> acc[4];
#pragma unroll
            for (int j = 0; j < 4; j++) wmma::fill_fragment(acc[j], 0.f);
#pragma unroll
            for (int p = 0; p < 3; p++) {
                const __nv_bfloat16* As = (p == 2) ? sAl : sAh;
                const __nv_bfloat16* Bs = (p == 1) ? sW2l : sW2h;
                for (int k = 0; k < 8; k++) {
                    wmma::fragment<wmma::matrix_a, 16, 16, 16, __nv_bfloat16, wmma::row_major> af;
                    wmma::load_matrix_sync(af, &As[r0 * WS + k * 16], WS);
#pragma unroll
                    for (int j = 0; j < 4; j++) {
                        wmma::fragment<wmma::matrix_b, 16, 16, 16, __nv_bfloat16, wmma::row_major> bf;
                        wmma::load_matrix_sync(bf, &Bs[k * 16 * WS + c0 + j * 16], WS);
                        wmma::mma_sync(acc[j], af, bf, acc[j]);
                    }
                }
            }
#pragma unroll
            for (int j = 0; j < 4; j++)
                wmma::store_matrix_sync(&sC[r0 * CS + c0 + j * 16], acc[j], CS,
                                        wmma::mem_row_major);
        }
        __syncthreads();

        // ---- epilogue: x2 = C + b2; pool RED (run-length); x_cur = x2 + vn ----
        {
            const float bx = b2s[2 * col2], by = b2s[2 * col2 + 1];
            float px = 0.f, py = 0.f;
            int curb = -1;
            for (int r = 0; r < 16; r++) {
                const int lrow = seg * 16 + r;
                const int grow = row0 + lrow;
                if (grow >= NN) break;
                const float vx = sC[lrow * CS + 2 * col2] + bx;
                const float vy = sC[lrow * CS + 2 * col2 + 1] + by;
                const int b = sB[lrow];
                if (b != curb) {
                    if (curb >= 0)
                        red_v2(&g_pool[curb * JKD + layer * DD + 2 * col2], px, py);
                    curb = b; px = 0.f; py = 0.f;
                }
                px += vx; py += vy;
                if (vn_next)
                    *reinterpret_cast<float2*>(&g_xcur[(size_t)grow * DD + 2 * col2]) =
                        make_float2(vx + vn2.x, vy + vn2.y);
            }
            if (curb >= 0)
                red_v2(&g_pool[curb * JKD + layer * DD + 2 * col2], px, py);
        }
    }
}

// ---------------------------------------------------------------------------
// Head (unchanged; re-zeroes g_pool rows for graph-replay determinism)
// ---------------------------------------------------------------------------
__device__ __forceinline__ float2 block_sum2(float a, float b) {
    __shared__ float2 sred[8];
    const int lane = threadIdx.x & 31, w = threadIdx.x >> 5;
#pragma unroll
    for (int o = 16; o; o >>= 1) {
        a += __shfl_down_sync(0xffffffffu, a, o);
        b += __shfl_down_sync(0xffffffffu, b, o);
    }
    if (lane == 0) sred[w] = make_float2(a, b);
    __syncthreads();
    if (w == 0) {
        float2 s = (lane < 8) ? sred[lane] : make_float2(0.f, 0.f);
#pragma unroll
        for (int o = 4; o; o >>= 1) {
            s.x += __shfl_down_sync(0xffffffffu, s.x, o);
            s.y += __shfl_down_sync(0xffffffffu, s.y, o);
        }
        if (lane == 0) sred[0] = s;
    }
    __syncthreads();
    const float2 r = sred[0];
    __syncthreads();
    return r;
}

__global__ __launch_bounds__(256) void head_kernel(
    const float* __restrict__ w1, const float* __restrict__ b1,
    const float* __restrict__ ga1, const float* __restrict__ be1,
    const float* __restrict__ w2, const float* __restrict__ b2,
    const float* __restrict__ ga2, const float* __restrict__ be2,
    const float* __restrict__ ow, const float* __restrict__ ob,
    float* __restrict__ out)
{
    __shared__ float sg[JKD];
    __shared__ float s1[256];
    const int g = blockIdx.x, t = threadIdx.x;

    for (int i = t; i < JKD; i += 256) {
        sg[i] = g_pool[g * JKD + i];
        g_pool[g * JKD + i] = 0.f;
    }
    __syncthreads();

    float acc = b1[t];
#pragma unroll 4
    for (int k = 0; k < JKD; k++) acc = fmaf(sg[k], w1[k * 256 + t], acc);
    float2 s = block_sum2(acc, acc * acc);
    float mu = s.x * (1.f / 256.f);
    float var = s.y * (1.f / 256.f) - mu * mu;
    s1[t] = fmaxf((acc - mu) * rsqrtf(var + 1e-5f) * ga1[t] + be1[t], 0.f);
    __syncthreads();

    float acc2 = 0.f;
    if (t < 128) {
        acc2 = b2[t];
#pragma unroll 4
        for (int k = 0; k < 256; k++) acc2 = fmaf(s1[k], w2[k * 128 + t], acc2);
    }
    const float cva = (t < 128) ? acc2 : 0.f;
    float2 s2 = block_sum2(cva, cva * cva);
    float mu2 = s2.x * (1.f / 128.f);
    float var2 = s2.y * (1.f / 128.f) - mu2 * mu2;
    float v2 = 0.f;
    if (t < 128) v2 = fmaxf((acc2 - mu2) * rsqrtf(var2 + 1e-5f) * ga2[t] + be2[t], 0.f);

    const float p = (t < 128) ? v2 * ow[t] : 0.f;
    float2 s3 = block_sum2(p, 0.f);
    if (t == 0) out[g] = s3.x + ob[0];
}

// ---------------------------------------------------------------------------
extern "C" void kernel_launch(void* const* d_in, const int* in_sizes, int n_in,
                              void* d_out, int out_size) {
    (void)in_sizes; (void)n_in; (void)out_size;
    const float* x     = (const float*)d_in[0];
    const int*   ei    = (const int*)d_in[1];
    const float* ea    = (const float*)d_in[2];
    const int*   batch = (const int*)d_in[3];
    const float* vn    = (const float*)d_in[4];
    const float* ew    = (const float*)d_in[5];
    const float* ebias = (const float*)d_in[6];
    const float* eps   = (const float*)d_in[7];
    const float* mw1   = (const float*)d_in[8];
    const float* mb1   = (const float*)d_in[9];
    const float* mw2   = (const float*)d_in[10];
    const float* mb2   = (const float*)d_in[11];
    const float* lw1   = (const float*)d_in[12];
    const float* lb1   = (const float*)d_in[13];
    const float* ln1g  = (const float*)d_in[14];
    const float* ln1b  = (const float*)d_in[15];
    const float* lw2   = (const float*)d_in[16];
    const float* lb2   = (const float*)d_in[17];
    const float* ln2g  = (const float*)d_in[18];
    const float* ln2b  = (const float*)d_in[19];
    const float* ow    = (const float*)d_in[20];
    const float* ob    = (const float*)d_in[21];
    float* out = (float*)d_out;

    int nsm = 148;
    cudaDeviceGetAttribute(&nsm, cudaDevAttrMultiProcessorCount, 0);

    // 4 weight bufs + 2 A bufs + C staging (all stride-136)
    const int node_smem = (4 * DD * WS + 2 * TROWS * WS) * 2 + TROWS * CS * 4;  // 208896 B
    cudaFuncSetAttribute(node_wmma, cudaFuncAttributeMaxDynamicSharedMemorySize, node_smem);

    k_hist<<<(EE + 255) / 256, 256>>>(ei);
    k_scan_single<<<1, 1024>>>();
    k_scatter_init<<<(NN * DD / 4 + 255) / 256, 256>>>(ei, ea, x, vn);

    for (int i = 0; i < LLAYERS; i++) {
        agg_kernel<<<nsm * 2, 256>>>(ew + i * EDIM * DD, ebias + i * DD);
        node_wmma<<<nsm, 256, node_smem>>>(
            mw1 + i * DD * DD, mb1 + i * DD,
            mw2 + i * DD * DD, mb2 + i * DD,
            eps + i,
            (i < LLAYERS - 1) ? (vn + (i + 1) * DD) : nullptr,
            batch, i);
    }

    head_kernel<<<GG, 256>>>(lw1, lb1, ln1g, ln1b, lw2, lb2, ln2g, ln2b, ow, ob, out);
}